// round 15
// baseline (speedup 1.0000x reference)
#include <cuda_runtime.h>
#include <cuda_bf16.h>
#include <cstdint>
#include <cstddef>

#define B_     8
#define LC_    2048
#define LQ_    128
#define D_     256
#define D8_    1024
#define NROWS  16384
#define NEGV   (-10000000000.0f)

// ================= scratch (static device globals; no allocation) =================
__device__ float g_sc[NROWS];
__device__ float g_sq[B_ * LQ_];
__device__ float g_rowmax[NROWS];
__device__ float g_c2q[NROWS * D_];
__device__ float g_q2c[B_ * D_];
__device__ float g_q2cw[B_ * LC_];
__device__ float g_q2cp[B_ * 32 * D_];
__device__ int   g_rows[NROWS];
__device__ int   g_cntb[B_];
__device__ int   g_offb[B_ + 1];
__device__ int   g_nact;
__device__ int   g_maskbyte;
__device__ __nv_bfloat16 g_Xh[(size_t)NROWS * D8_];
__device__ __nv_bfloat16 g_Xl[(size_t)NROWS * D8_];
__device__ __nv_bfloat16 g_Hh[(size_t)NROWS * D8_];
__device__ __nv_bfloat16 g_Hl[(size_t)NROWS * D8_];
__device__ __nv_bfloat16 g_Wh[2][(size_t)D8_ * D8_];
__device__ __nv_bfloat16 g_Wl[2][(size_t)D8_ * D8_];

__device__ __forceinline__ float maskval(const void* p, int mb, int i) {
    return mb ? (float)((const unsigned char*)p)[i]
              : (float)((const int*)p)[i];
}

__device__ __forceinline__ uint32_t smem_u32(const void* smem_ptr) {
    uint32_t addr;
    asm("{ .reg .u64 tmp; cvta.to.shared.u64 tmp, %1; cvt.u32.u64 %0, tmp; }"
        : "=r"(addr) : "l"(smem_ptr));
    return addr;
}

#define CP16(s, g) asm volatile("cp.async.ca.shared.global [%0], [%1], 16;" :: "r"(s), "l"(g))
#define CP_COMMIT() asm volatile("cp.async.commit_group;" ::: "memory")
#define CP_WAIT(n)  asm volatile("cp.async.wait_group %0;" :: "n"(n) : "memory")

#define LDSM_X4(r0,r1,r2,r3, addr) \
    asm volatile("ldmatrix.sync.aligned.m8n8.x4.shared.b16 {%0,%1,%2,%3}, [%4];" \
        : "=r"(r0),"=r"(r1),"=r"(r2),"=r"(r3) : "r"(addr))
#define LDSM_X2(r0,r1, addr) \
    asm volatile("ldmatrix.sync.aligned.m8n8.x2.shared.b16 {%0,%1}, [%2];" \
        : "=r"(r0),"=r"(r1) : "r"(addr))

#define MMA16816(c, a, b) \
    asm volatile("mma.sync.aligned.m16n8k16.row.col.f32.bf16.bf16.f32 " \
        "{%0,%1,%2,%3}, {%4,%5,%6,%7}, {%8,%9}, {%0,%1,%2,%3};" \
        : "+f"((c)[0]),"+f"((c)[1]),"+f"((c)[2]),"+f"((c)[3]) \
        : "r"((a)[0]),"r"((a)[1]),"r"((a)[2]),"r"((a)[3]), "r"((b)[0]),"r"((b)[1]))

// ---------------- kernel 0: detect mask dtype ----------------
__global__ void k_detect(const unsigned int* cm) {
    __shared__ int f;
    if (threadIdx.x == 0) f = 0;
    __syncthreads();
    int any = 0;
    for (int i = threadIdx.x; i < NROWS / 4; i += blockDim.x)
        any |= (cm[i] > 1u) ? 1 : 0;
    if (any) atomicOr(&f, 1);
    __syncthreads();
    if (threadIdx.x == 0) g_maskbyte = f;
}

// ---------------- kernel 0b: per-batch active counts ----------------
__global__ void k_count(const void* cm) {
    __shared__ int red[256];
    int b = blockIdx.x, t = threadIdx.x;
    int mb = g_maskbyte;
    int cnt = 0;
    for (int i = t; i < LC_; i += 256)
        cnt += (maskval(cm, mb, b * LC_ + i) == 0.f) ? 1 : 0;
    red[t] = cnt; __syncthreads();
    for (int s = 128; s > 0; s >>= 1) { if (t < s) red[t] += red[t + s]; __syncthreads(); }
    if (t == 0) g_cntb[b] = red[0];
}

// ---------------- kernel 0c: prefix offsets ----------------
__global__ void k_off() {
    if (threadIdx.x == 0) {
        int s = 0;
        for (int b = 0; b < B_; b++) { g_offb[b] = s; s += g_cntb[b]; }
        g_offb[B_] = s;
        g_nact = s;
    }
}

// ---------------- kernel 0d: deterministic packed fill (ballot scan) ----------------
__global__ void k_fill(const void* cm) {
    __shared__ int warpsums[8];
    int b = blockIdx.x, t = threadIdx.x;
    int lane = t & 31, wid = t >> 5;
    int mb = g_maskbyte;
    int base = g_offb[b];
    int running = 0;
    for (int g = 0; g < LC_ / 256; g++) {
        int row = b * LC_ + g * 256 + t;
        int a = (maskval(cm, mb, row) == 0.f) ? 1 : 0;
        unsigned bal = __ballot_sync(0xffffffffu, a);
        int rank = __popc(bal & ((1u << lane) - 1));
        if (lane == 0) warpsums[wid] = __popc(bal);
        __syncthreads();
        int wbase = 0, tot = 0;
#pragma unroll
        for (int w = 0; w < 8; w++) {
            int ws = warpsums[w];
            if (w < wid) wbase += ws;
            tot += ws;
        }
        if (a) g_rows[base + running + wbase + rank] = row;
        running += tot;
        __syncthreads();
    }
}

// ---------------- kernel 1: sc/sq matvecs ----------------
__global__ void k_scsq(const float* __restrict__ ctx, const float* __restrict__ qry,
                       const float* __restrict__ wsim) {
    int gw   = (blockIdx.x * blockDim.x + threadIdx.x) >> 5;
    int lane = threadIdx.x & 31;
    if (gw < NROWS) {
        const float* p = ctx + (size_t)gw * D_;
        float s = 0.f;
#pragma unroll
        for (int q = 0; q < 8; q++) { int d = lane + 32 * q; s += p[d] * wsim[d]; }
#pragma unroll
        for (int o = 16; o; o >>= 1) s += __shfl_xor_sync(0xffffffffu, s, o);
        if (lane == 0) g_sc[gw] = s;
    } else if (gw < NROWS + B_ * LQ_) {
        int w2 = gw - NROWS;
        const float* p = qry + (size_t)w2 * D_;
        float s = 0.f;
#pragma unroll
        for (int q = 0; q < 8; q++) { int d = lane + 32 * q; s += p[d] * wsim[D_ + d]; }
#pragma unroll
        for (int o = 16; o; o >>= 1) s += __shfl_xor_sync(0xffffffffu, s, o);
        if (lane == 0) g_sq[w2] = s;
    }
}

// ---------------- kernel 2: fused sim + softmax + c2q + rowmax ----------------
// Phase B split into two column-half passes: acc2[8][4] instead of [8][8],
// cutting peak registers (~130 -> <128) so 2 CTAs/SM fit naturally.
__global__ __launch_bounds__(256) void k_attn(
    const float* __restrict__ ctx, const float* __restrict__ qry,
    const void* qm_,
    const float* __restrict__ wsim, const float* __restrict__ bsim)
{
    __shared__ float sS[64 * 128];
    __shared__ float sT[3072];
    __shared__ float s_sc[64], s_sq[128], s_qm[128];
    __shared__ int   s_ridx[64];

    int t  = threadIdx.x;
    int b  = blockIdx.y;
    int it = blockIdx.x;
    int nb = g_cntb[b];
    if (it * 64 >= nb) return;
    int off    = g_offb[b];
    int nrows  = min(64, nb - it * 64);
    int mb     = g_maskbyte;

    if (t < 64) {
        int li = it * 64 + t;
        int r  = g_rows[off + (t < nrows ? li : it * 64)];
        s_ridx[t] = r;
        s_sc[t]   = g_sc[r];
    } else if (t < 192) {
        int j = t - 64;
        s_sq[j] = g_sq[b * LQ_ + j];
        s_qm[j] = maskval(qm_, mb, b * LQ_ + j);
    }
    __syncthreads();

    float* cwS = sT;
    float* qS  = sT + 1024;
    const float* wx    = wsim + 2 * D_;
    const float* qbase = qry + (size_t)b * LQ_ * D_;

    float acc[4][8];
#pragma unroll
    for (int i = 0; i < 4; i++)
#pragma unroll
        for (int j = 0; j < 8; j++) acc[i][j] = 0.f;

    int tr = (t >> 4) * 4;
    int tc = (t & 15) * 8;
    int lr = t >> 2;
    int lc = (t & 3) * 4;
    const float* crow = ctx + (size_t)s_ridx[lr] * D_;

    for (int d0 = 0; d0 < D_; d0 += 16) {
        float4 cv = *(const float4*)(crow + d0 + lc);
        float4 wv = *(const float4*)(wx + d0 + lc);
        cwS[(lc + 0) * 64 + lr] = cv.x * wv.x;
        cwS[(lc + 1) * 64 + lr] = cv.y * wv.y;
        cwS[(lc + 2) * 64 + lr] = cv.z * wv.z;
        cwS[(lc + 3) * 64 + lr] = cv.w * wv.w;
#pragma unroll
        for (int l = 0; l < 2; l++) {
            int j = lr + l * 64;
            float4 qv = *(const float4*)(qbase + (size_t)j * D_ + d0 + lc);
            qS[(lc + 0) * 128 + j] = qv.x;
            qS[(lc + 1) * 128 + j] = qv.y;
            qS[(lc + 2) * 128 + j] = qv.z;
            qS[(lc + 3) * 128 + j] = qv.w;
        }
        __syncthreads();
#pragma unroll
        for (int kk = 0; kk < 16; kk++) {
            float ra[4];
#pragma unroll
            for (int i = 0; i < 4; i++) ra[i] = cwS[kk * 64 + tr + i];
            float4 q0 = *(float4*)&qS[kk * 128 + tc];
            float4 q1 = *(float4*)&qS[kk * 128 + tc + 4];
            float rb[8] = {q0.x, q0.y, q0.z, q0.w, q1.x, q1.y, q1.z, q1.w};
#pragma unroll
            for (int i = 0; i < 4; i++)
#pragma unroll
                for (int j = 0; j < 8; j++) acc[i][j] += ra[i] * rb[j];
        }
        __syncthreads();
    }

    float bs = bsim[0];
#pragma unroll
    for (int i = 0; i < 4; i++) {
        float rowadd = s_sc[tr + i] + bs;
#pragma unroll
        for (int j = 0; j < 8; j++) {
            float v = acc[i][j] + rowadd + s_sq[tc + j];
            if (s_qm[tc + j] != 0.f) v = NEGV;
            sS[(tr + i) * 128 + tc + j] = v;
        }
    }
    __syncthreads();

    int lane = t & 31, warp = t >> 5;
#pragma unroll
    for (int rr = 0; rr < 8; rr++) {
        int r = warp * 8 + rr;
        float* row = sS + r * 128;
        float v0 = row[lane], v1 = row[lane + 32], v2 = row[lane + 64], v3 = row[lane + 96];
        float m = fmaxf(fmaxf(v0, v1), fmaxf(v2, v3));
#pragma unroll
        for (int o = 16; o; o >>= 1) m = fmaxf(m, __shfl_xor_sync(0xffffffffu, m, o));
        float e0 = __expf(v0 - m), e1 = __expf(v1 - m), e2 = __expf(v2 - m), e3 = __expf(v3 - m);
        float s = e0 + e1 + e2 + e3;
#pragma unroll
        for (int o = 16; o; o >>= 1) s += __shfl_xor_sync(0xffffffffu, s, o);
        float inv = 1.f / s;
        row[lane]      = e0 * inv;
        row[lane + 32] = e1 * inv;
        row[lane + 64] = e2 * inv;
        row[lane + 96] = e3 * inv;
        if (lane == 0 && r < nrows) g_rowmax[b * LC_ + it * 64 + r] = m;
    }
    __syncthreads();

    // ---- phase B: c2q = P @ Q in two column-half passes ----
    float* qS2 = sT;   // [8][128] per chunk
    int tr2 = (t >> 5) * 8;
    int tc2 = (t & 31) * 4;
    int jr  = t >> 5;           // 0..7
    int nc  = (t & 31) * 4;     // 0..124

#pragma unroll
    for (int half = 0; half < 2; half++) {
        int c0 = half * 128;
        float acc2[8][4];
#pragma unroll
        for (int i = 0; i < 8; i++)
#pragma unroll
            for (int j = 0; j < 4; j++) acc2[i][j] = 0.f;

        for (int j0 = 0; j0 < LQ_; j0 += 8) {
            *(float4*)&qS2[jr * 128 + nc] =
                *(const float4*)(qbase + (size_t)(j0 + jr) * D_ + c0 + nc);
            __syncthreads();
#pragma unroll
            for (int kk = 0; kk < 8; kk++) {
                float ra[8];
#pragma unroll
                for (int i = 0; i < 8; i++) ra[i] = sS[(tr2 + i) * 128 + j0 + kk];
                float4 q0 = *(float4*)&qS2[kk * 128 + tc2];
                float rb[4] = {q0.x, q0.y, q0.z, q0.w};
#pragma unroll
                for (int i = 0; i < 8; i++)
#pragma unroll
                    for (int j = 0; j < 4; j++) acc2[i][j] += ra[i] * rb[j];
            }
            __syncthreads();
        }
#pragma unroll
        for (int i = 0; i < 8; i++) {
            if (tr2 + i < nrows) {
                float* dst = g_c2q + (size_t)(off + it * 64 + tr2 + i) * D_ + c0 + tc2;
                *(float4*)dst = make_float4(acc2[i][0], acc2[i][1], acc2[i][2], acc2[i][3]);
            }
        }
    }
}

// ---------------- kernels 3a-c: q2c over ACTIVE rows ----------------
__global__ void k_q2cw() {
    __shared__ float red[256];
    int b = blockIdx.x, t = threadIdx.x;
    int nb = g_cntb[b];
    if (nb == 0) return;
    const float* rm = g_rowmax + b * LC_;

    float m = -3.4e38f;
    for (int i = t; i < nb; i += 256) m = fmaxf(m, rm[i]);
    red[t] = m; __syncthreads();
    for (int s = 128; s > 0; s >>= 1) { if (t < s) red[t] = fmaxf(red[t], red[t + s]); __syncthreads(); }
    m = red[0]; __syncthreads();

    float sum = 0.f;
    for (int i = t; i < nb; i += 256) sum += __expf(rm[i] - m);
    red[t] = sum; __syncthreads();
    for (int s = 128; s > 0; s >>= 1) { if (t < s) red[t] += red[t + s]; __syncthreads(); }
    float inv = 1.f / red[0];
    __syncthreads();
    for (int i = t; i < nb; i += 256)
        g_q2cw[b * LC_ + i] = __expf(rm[i] - m) * inv;
}

__global__ void k_q2cp(const float* __restrict__ ctx) {
    int chunk = blockIdx.x, b = blockIdx.y, t = threadIdx.x;
    int nb  = g_cntb[b];
    int off = g_offb[b];
    int i0  = chunk * 64;
    int i1  = min(i0 + 64, nb);
    const float* w = g_q2cw + b * LC_;
    float acc = 0.f;
    for (int i = i0; i < i1; i++)
        acc += w[i] * ctx[(size_t)g_rows[off + i] * D_ + t];
    g_q2cp[((size_t)b * 32 + chunk) * D_ + t] = acc;
}

__global__ void k_q2cf() {
    int b = blockIdx.x, t = threadIdx.x;
    float acc = 0.f;
#pragma unroll
    for (int c = 0; c < 32; c++)
        acc += g_q2cp[((size_t)b * 32 + c) * D_ + t];
    g_q2c[b * D_ + t] = acc;
}

// ---------------- kernel 4: zero masked output rows ----------------
__global__ void k_zero(const void* cm, float* __restrict__ out) {
    int row = blockIdx.x;
    if (maskval(cm, g_maskbyte, row) != 0.f)
        ((float4*)out)[(size_t)row * 256 + threadIdx.x] = make_float4(0.f, 0.f, 0.f, 0.f);
}

// ---------------- kernel 5: build X as bf16 hi/lo split (packed) ----------------
__global__ void k_buildX(const float* __restrict__ ctx) {
    int m = blockIdx.x;
    if (m >= g_nact) return;
    int r = g_rows[m];
    int b = r >> 11;
    int t = threadIdx.x;
    int seg = t >> 6, kk = t & 63;
    const float4* c4 = (const float4*)ctx + (size_t)r * 64;
    float4 v;
    if (seg == 0) v = c4[kk];
    else if (seg == 1) v = ((const float4*)g_c2q)[(size_t)m * 64 + kk];
    else if (seg == 2) {
        float4 a = c4[kk]; float4 q = ((const float4*)g_c2q)[(size_t)m * 64 + kk];
        v = make_float4(a.x * q.x, a.y * q.y, a.z * q.z, a.w * q.w);
    } else {
        float4 a = c4[kk]; float4 q = ((const float4*)g_q2c)[b * 64 + kk];
        v = make_float4(a.x * q.x, a.y * q.y, a.z * q.z, a.w * q.w);
    }
    float vv[4] = {v.x, v.y, v.z, v.w};
    __nv_bfloat16 h[4], l[4];
#pragma unroll
    for (int i = 0; i < 4; i++) {
        h[i] = __float2bfloat16(vv[i]);
        l[i] = __float2bfloat16(vv[i] - __bfloat162float(h[i]));
    }
    size_t offb = (size_t)m * D8_ + t * 4;
    __nv_bfloat162 h0; h0.x = h[0]; h0.y = h[1];
    __nv_bfloat162 h1; h1.x = h[2]; h1.y = h[3];
    __nv_bfloat162 l0; l0.x = l[0]; l0.y = l[1];
    __nv_bfloat162 l1; l1.x = l[2]; l1.y = l[3];
    *(__nv_bfloat162*)(g_Xh + offb)     = h0;
    *(__nv_bfloat162*)(g_Xh + offb + 2) = h1;
    *(__nv_bfloat162*)(g_Xl + offb)     = l0;
    *(__nv_bfloat162*)(g_Xl + offb + 2) = l1;
}

// ---------------- kernel 5b: transpose + bf16-split weights ----------------
__global__ void k_wconv(const float* __restrict__ Wi, const float* __restrict__ Wo) {
    __shared__ float tile[32][33];
    const float* W = blockIdx.z ? Wo : Wi;
    __nv_bfloat16* Wh = g_Wh[blockIdx.z];
    __nv_bfloat16* Wl = g_Wl[blockIdx.z];
    int k0 = blockIdx.y * 32, n0 = blockIdx.x * 32;
    int t = threadIdx.x;
    int r = t >> 5, c = t & 31;
#pragma unroll
    for (int i = 0; i < 4; i++)
        tile[r + i * 8][c] = W[(size_t)(k0 + r + i * 8) * D8_ + n0 + c];
    __syncthreads();
#pragma unroll
    for (int i = 0; i < 4; i++) {
        int n = r + i * 8;
        float v = tile[c][n];
        __nv_bfloat16 h = __float2bfloat16(v);
        size_t off = (size_t)(n0 + n) * D8_ + k0 + c;
        Wh[off] = h;
        Wl[off] = __float2bfloat16(v - __bfloat162float(h));
    }
}

// ---------------- kernel 6: mma.sync bf16x3 GEMM, 128x128 tile, BK=64, 2-stage (round-6 exact) ----------------
#define TROW    144
#define ARR_B   (128 * TROW)
#define STAGE_B (4 * ARR_B)
#define GEMM_SMEM_BYTES (2 * STAGE_B)   // 147456

template <int MODE>
__global__ __launch_bounds__(256, 1) void k_gemm_mma(
    const float* __restrict__ bias, float* __restrict__ out)
{
    extern __shared__ char smem[];
    const int M = g_nact;
    const int bm = blockIdx.y, bn = blockIdx.x;
    if (bm * 128 >= M) return;

    uint32_t sbase = smem_u32(smem);

    int t = threadIdx.x;
    int wid = t >> 5, lane = t & 31;
    int warp_m = wid >> 2;
    int warp_n = wid & 3;

    const __nv_bfloat16* AhG = (MODE == 0) ? g_Xh : g_Hh;
    const __nv_bfloat16* AlG = (MODE == 0) ? g_Xl : g_Hl;
    const __nv_bfloat16* BhG = g_Wh[MODE];
    const __nv_bfloat16* BlG = g_Wl[MODE];

    int lrow  = t >> 1;
    int lcolb = (t & 1) * 32;
    int arow  = bm * 128 + lrow;
    if (arow >= M) arow = M - 1;
    const __nv_bfloat16* gAh = AhG + (size_t)arow * D8_ + lcolb;
    const __nv_bfloat16* gAl = AlG + (size_t)arow * D8_ + lcolb;
    const __nv_bfloat16* gBh = BhG + (size_t)(bn * 128 + lrow) * D8_ + lcolb;
    const __nv_bfloat16* gBl = BlG + (size_t)(bn * 128 + lrow) * D8_ + lcolb;
    uint32_t s_off = lrow * TROW + lcolb * 2;

#define LOAD_CHUNK(k0, stg) do { \
    uint32_t sb = sbase + (stg) * STAGE_B + s_off; \
    _Pragma("unroll") \
    for (int j = 0; j < 4; j++) { \
        CP16(sb + 0 * ARR_B + j * 16, gAh + (k0) + j * 8); \
        CP16(sb + 1 * ARR_B + j * 16, gAl + (k0) + j * 8); \
        CP16(sb + 2 * ARR_B + j * 16, gBh + (k0) + j * 8); \
        CP16(sb + 3 * ARR_B + j * 16, gBl + (k0) + j * 8); \
    } \
    CP_COMMIT(); \
} while (0)

    float acc[4][4][4];
#pragma unroll
    for (int mi = 0; mi < 4; mi++)
#pragma unroll
        for (int ni = 0; ni < 4; ni++)
#pragma unroll
            for (int k = 0; k < 4; k++) acc[mi][ni][k] = 0.f;

    uint32_t aAddrBase = (warp_m * 64 + (lane & 15)) * TROW + ((lane >> 4) & 1) * 16;
    uint32_t bAddrBase = 2 * ARR_B + (warp_n * 32 + (lane & 7)) * TROW + ((lane >> 3) & 1) * 16;

    LOAD_CHUNK(0, 0);

    for (int chunk = 0; chunk < 16; chunk++) {
        int buf = chunk & 1;
        if (chunk + 1 < 16) {
            LOAD_CHUNK((chunk + 1) * 64, buf ^ 1);
            CP_WAIT(1);
        } else {
            CP_WAIT(0);
        }
        __syncthreads();

        uint32_t st = sbase + buf * STAGE_B;
#pragma unroll
        for (int kk = 0; kk < 4; kk++) {
            uint32_t bh[4][2], bl[4][2];
            uint32_t bAddr = st + bAddrBase + kk * 32;
#pragma unroll
            for (int ni = 0; ni < 4; ni++) {
                LDSM_X2(bh[ni][0], bh[ni][1], bAddr + ni * 8 * TROW);
                LDSM_X2(bl[ni][0], bl[ni][1], bAddr + ni * 8 * TROW + ARR_B);
            }
#pragma unroll
            for (int mi = 0; mi < 4; mi++) {
                uint32_t aAddr = st + aAddrBase + mi * 16 * TROW + kk * 32;
                uint32_t ah[4], al[4];
                LDSM_X4(ah[0], ah[1], ah[2], ah[3], aAddr);
                LDSM_X4(al[0], al[1], al[2], al[3], aAddr + ARR_B);
#pragma unroll
                for (int ni = 0; ni < 4; ni++) {
                    MMA16816(acc[mi][ni], ah, bh[ni]);
                    MMA16816(acc[mi][ni], ah, bl[ni]);
                    MMA16816(acc[mi][ni], al, bh[ni]);
                }
            }
        }
        __syncthreads();
    }
#undef LOAD_CHUNK

    int q   = lane >> 2;
    int cp2 = (lane & 3) * 2;
#pragma unroll
    for (int ni = 0; ni < 4; ni++) {
        int col = bn * 128 + warp_n * 32 + ni * 8 + cp2;
        float bv0 = bias[col], bv1 = bias[col + 1];
#pragma unroll
        for (int mi = 0; mi < 4; mi++) {
#pragma unroll
            for (int h = 0; h < 2; h++) {
                int lm   = warp_m * 64 + mi * 16 + q + h * 8;
                int grow = bm * 128 + lm;
                if (grow < M) {
                    float v0 = acc[mi][ni][h * 2 + 0] + bv0;
                    float v1 = acc[mi][ni][h * 2 + 1] + bv1;
                    if (MODE == 0) {
                        v0 = fmaxf(v0, 0.f); v1 = fmaxf(v1, 0.f);
                        __nv_bfloat16 h0 = __float2bfloat16(v0);
                        __nv_bfloat16 h1 = __float2bfloat16(v1);
                        __nv_bfloat162 hh; hh.x = h0; hh.y = h1;
                        __nv_bfloat162 ll;
                        ll.x = __float2bfloat16(v0 - __bfloat162float(h0));
                        ll.y = __float2bfloat16(v1 - __bfloat162float(h1));
                        size_t off = (size_t)grow * D8_ + col;
                        *(__nv_bfloat162*)(g_Hh + off) = hh;
                        *(__nv_bfloat162*)(g_Hl + off) = ll;
                    } else {
                        float2 vv; vv.x = v0; vv.y = v1;
                        *(float2*)(out + (size_t)g_rows[grow] * D8_ + col) = vv;
                    }
                }
            }
        }
    }
}

// ---------------- launch (fork/join streams inside graph capture, round-12 graph) ----------------
extern "C" void kernel_launch(void* const* d_in, const int* in_sizes, int n_in,
                              void* d_out, int out_size) {
    const float* ctx  = (const float*)d_in[0];
    const void*  cm   = d_in[1];
    const float* qry  = (const float*)d_in[2];
    const void*  qm   = d_in[3];
    const float* wsim = (const float*)d_in[4];
    const float* bsim = (const float*)d_in[5];
    const float* wi   = (const float*)d_in[6];
    const float* bi   = (const float*)d_in[7];
    const float* wo   = (const float*)d_in[8];
    const float* bo   = (const float*)d_in[9];
    float* out = (float*)d_out;

    static cudaStream_t sSide = nullptr, sZero = nullptr;
    static cudaEvent_t evFork = nullptr, evSide = nullptr, evDet = nullptr, evZero = nullptr;
    if (sSide == nullptr) {
        cudaStreamCreateWithFlags(&sSide, cudaStreamNonBlocking);
        cudaStreamCreateWithFlags(&sZero, cudaStreamNonBlocking);
        cudaEventCreateWithFlags(&evFork, cudaEventDisableTiming);
        cudaEventCreateWithFlags(&evSide, cudaEventDisableTiming);
        cudaEventCreateWithFlags(&evDet,  cudaEventDisableTiming);
        cudaEventCreateWithFlags(&evZero, cudaEventDisableTiming);
        cudaFuncSetAttribute(k_gemm_mma<0>, cudaFuncAttributeMaxDynamicSharedMemorySize, GEMM_SMEM_BYTES);
        cudaFuncSetAttribute(k_gemm_mma<1>, cudaFuncAttributeMaxDynamicSharedMemorySize, GEMM_SMEM_BYTES);
    }

    // fork: side stream does scsq (no mask dep) + wconv (fully independent)
    cudaEventRecord(evFork, 0);
    cudaStreamWaitEvent(sSide, evFork, 0);
    k_scsq<<<(NROWS + B_ * LQ_) / 8, 256, 0, sSide>>>(ctx, qry, wsim);
    k_wconv<<<dim3(32, 32, 2), 256, 0, sSide>>>(wi, wo);
    cudaEventRecord(evSide, sSide);

    // main: mask prolog chain; k_zero overlapped on its own stream
    k_detect<<<1, 256>>>((const unsigned int*)cm);
    cudaEventRecord(evDet, 0);
    cudaStreamWaitEvent(sZero, evDet, 0);
    k_zero<<<NROWS, 256, 0, sZero>>>(cm, out);
    cudaEventRecord(evZero, sZero);

    k_count<<<B_, 256>>>(cm);
    k_off<<<1, 32>>>();
    k_fill<<<B_, 256>>>(cm);

    // join side (attn needs g_sc/g_sq; gemm0 needs W converted)
    cudaStreamWaitEvent(0, evSide, 0);
    k_attn<<<dim3(32, B_), 256>>>(ctx, qry, qm, wsim, bsim);
    k_q2cw<<<B_, 256>>>();
    k_q2cp<<<dim3(32, B_), 256>>>(ctx);
    k_q2cf<<<B_, 256>>>();
    k_buildX<<<NROWS, 256>>>(ctx);
    k_gemm_mma<0><<<dim3(8, NROWS / 128), 256, GEMM_SMEM_BYTES>>>(bi, nullptr);
    cudaStreamWaitEvent(0, evZero, 0);
    k_gemm_mma<1><<<dim3(8, NROWS / 128), 256, GEMM_SMEM_BYTES>>>(bo, out);
}

// round 16
// speedup vs baseline: 1.0542x; 1.0542x over previous
#include <cuda_runtime.h>
#include <cuda_bf16.h>
#include <cstdint>
#include <cstddef>

#define B_     8
#define LC_    2048
#define LQ_    128
#define D_     256
#define D8_    1024
#define NROWS  16384
#define NEGV   (-10000000000.0f)

// ================= scratch (static device globals; no allocation) =================
__device__ float g_sc[NROWS];
__device__ float g_sq[B_ * LQ_];
__device__ float g_rowmax[NROWS];
__device__ float g_c2q[NROWS * D_];
__device__ float g_q2c[B_ * D_];
__device__ float g_q2cw[B_ * LC_];
__device__ float g_q2cp[B_ * 32 * D_];
__device__ int   g_rows[NROWS];
__device__ int   g_cntb[B_];
__device__ int   g_offb[B_ + 1];
__device__ int   g_nact;
__device__ int   g_maskbyte;
__device__ __nv_bfloat16 g_Xh[(size_t)NROWS * D8_];
__device__ __nv_bfloat16 g_Xl[(size_t)NROWS * D8_];
__device__ __nv_bfloat16 g_Hh[(size_t)NROWS * D8_];
__device__ __nv_bfloat16 g_Hl[(size_t)NROWS * D8_];
__device__ __nv_bfloat16 g_Wh[2][(size_t)D8_ * D8_];
__device__ __nv_bfloat16 g_Wl[2][(size_t)D8_ * D8_];

__device__ __forceinline__ float maskval(const void* p, int mb, int i) {
    return mb ? (float)((const unsigned char*)p)[i]
              : (float)((const int*)p)[i];
}

__device__ __forceinline__ uint32_t smem_u32(const void* smem_ptr) {
    uint32_t addr;
    asm("{ .reg .u64 tmp; cvta.to.shared.u64 tmp, %1; cvt.u32.u64 %0, tmp; }"
        : "=r"(addr) : "l"(smem_ptr));
    return addr;
}

#define CP16(s, g) asm volatile("cp.async.ca.shared.global [%0], [%1], 16;" :: "r"(s), "l"(g))
#define CP_COMMIT() asm volatile("cp.async.commit_group;" ::: "memory")
#define CP_WAIT(n)  asm volatile("cp.async.wait_group %0;" :: "n"(n) : "memory")

#define LDSM_X4(r0,r1,r2,r3, addr) \
    asm volatile("ldmatrix.sync.aligned.m8n8.x4.shared.b16 {%0,%1,%2,%3}, [%4];" \
        : "=r"(r0),"=r"(r1),"=r"(r2),"=r"(r3) : "r"(addr))
#define LDSM_X2(r0,r1, addr) \
    asm volatile("ldmatrix.sync.aligned.m8n8.x2.shared.b16 {%0,%1}, [%2];" \
        : "=r"(r0),"=r"(r1) : "r"(addr))

#define MMA16816(c, a, b) \
    asm volatile("mma.sync.aligned.m16n8k16.row.col.f32.bf16.bf16.f32 " \
        "{%0,%1,%2,%3}, {%4,%5,%6,%7}, {%8,%9}, {%0,%1,%2,%3};" \
        : "+f"((c)[0]),"+f"((c)[1]),"+f"((c)[2]),"+f"((c)[3]) \
        : "r"((a)[0]),"r"((a)[1]),"r"((a)[2]),"r"((a)[3]), "r"((b)[0]),"r"((b)[1]))

// ---------------- kernel 0: detect mask dtype ----------------
__global__ void k_detect(const unsigned int* cm) {
    __shared__ int f;
    if (threadIdx.x == 0) f = 0;
    __syncthreads();
    int any = 0;
    for (int i = threadIdx.x; i < NROWS / 4; i += blockDim.x)
        any |= (cm[i] > 1u) ? 1 : 0;
    if (any) atomicOr(&f, 1);
    __syncthreads();
    if (threadIdx.x == 0) g_maskbyte = f;
}

// ---------------- kernel 0b: per-batch active counts ----------------
__global__ void k_count(const void* cm) {
    __shared__ int red[256];
    int b = blockIdx.x, t = threadIdx.x;
    int mb = g_maskbyte;
    int cnt = 0;
    for (int i = t; i < LC_; i += 256)
        cnt += (maskval(cm, mb, b * LC_ + i) == 0.f) ? 1 : 0;
    red[t] = cnt; __syncthreads();
    for (int s = 128; s > 0; s >>= 1) { if (t < s) red[t] += red[t + s]; __syncthreads(); }
    if (t == 0) g_cntb[b] = red[0];
}

// ---------------- kernel 0c: prefix offsets ----------------
__global__ void k_off() {
    if (threadIdx.x == 0) {
        int s = 0;
        for (int b = 0; b < B_; b++) { g_offb[b] = s; s += g_cntb[b]; }
        g_offb[B_] = s;
        g_nact = s;
    }
}

// ---------------- kernel 0d: deterministic packed fill (ballot scan) ----------------
__global__ void k_fill(const void* cm) {
    __shared__ int warpsums[8];
    int b = blockIdx.x, t = threadIdx.x;
    int lane = t & 31, wid = t >> 5;
    int mb = g_maskbyte;
    int base = g_offb[b];
    int running = 0;
    for (int g = 0; g < LC_ / 256; g++) {
        int row = b * LC_ + g * 256 + t;
        int a = (maskval(cm, mb, row) == 0.f) ? 1 : 0;
        unsigned bal = __ballot_sync(0xffffffffu, a);
        int rank = __popc(bal & ((1u << lane) - 1));
        if (lane == 0) warpsums[wid] = __popc(bal);
        __syncthreads();
        int wbase = 0, tot = 0;
#pragma unroll
        for (int w = 0; w < 8; w++) {
            int ws = warpsums[w];
            if (w < wid) wbase += ws;
            tot += ws;
        }
        if (a) g_rows[base + running + wbase + rank] = row;
        running += tot;
        __syncthreads();
    }
}

// ---------------- kernel 1: sc/sq matvecs ----------------
__global__ void k_scsq(const float* __restrict__ ctx, const float* __restrict__ qry,
                       const float* __restrict__ wsim) {
    int gw   = (blockIdx.x * blockDim.x + threadIdx.x) >> 5;
    int lane = threadIdx.x & 31;
    if (gw < NROWS) {
        const float* p = ctx + (size_t)gw * D_;
        float s = 0.f;
#pragma unroll
        for (int q = 0; q < 8; q++) { int d = lane + 32 * q; s += p[d] * wsim[d]; }
#pragma unroll
        for (int o = 16; o; o >>= 1) s += __shfl_xor_sync(0xffffffffu, s, o);
        if (lane == 0) g_sc[gw] = s;
    } else if (gw < NROWS + B_ * LQ_) {
        int w2 = gw - NROWS;
        const float* p = qry + (size_t)w2 * D_;
        float s = 0.f;
#pragma unroll
        for (int q = 0; q < 8; q++) { int d = lane + 32 * q; s += p[d] * wsim[D_ + d]; }
#pragma unroll
        for (int o = 16; o; o >>= 1) s += __shfl_xor_sync(0xffffffffu, s, o);
        if (lane == 0) g_sq[w2] = s;
    }
}

// ---------------- kernel 2: fused sim + softmax + c2q + rowmax (ACTIVE rows only) ----------------
__global__ __launch_bounds__(256) void k_attn(
    const float* __restrict__ ctx, const float* __restrict__ qry,
    const void* qm_,
    const float* __restrict__ wsim, const float* __restrict__ bsim)
{
    __shared__ float sS[64 * 128];
    __shared__ float sT[3072];
    __shared__ float s_sc[64], s_sq[128], s_qm[128];
    __shared__ int   s_ridx[64];

    int t  = threadIdx.x;
    int b  = blockIdx.y;
    int it = blockIdx.x;
    int nb = g_cntb[b];
    if (it * 64 >= nb) return;
    int off    = g_offb[b];
    int nrows  = min(64, nb - it * 64);
    int mb     = g_maskbyte;

    if (t < 64) {
        int li = it * 64 + t;
        int r  = g_rows[off + (t < nrows ? li : it * 64)];
        s_ridx[t] = r;
        s_sc[t]   = g_sc[r];
    } else if (t < 192) {
        int j = t - 64;
        s_sq[j] = g_sq[b * LQ_ + j];
        s_qm[j] = maskval(qm_, mb, b * LQ_ + j);
    }
    __syncthreads();

    float* cwS = sT;
    float* qS  = sT + 1024;
    const float* wx    = wsim + 2 * D_;
    const float* qbase = qry + (size_t)b * LQ_ * D_;

    float acc[4][8];
#pragma unroll
    for (int i = 0; i < 4; i++)
#pragma unroll
        for (int j = 0; j < 8; j++) acc[i][j] = 0.f;

    int tr = (t >> 4) * 4;
    int tc = (t & 15) * 8;
    int lr = t >> 2;
    int lc = (t & 3) * 4;
    const float* crow = ctx + (size_t)s_ridx[lr] * D_;

    for (int d0 = 0; d0 < D_; d0 += 16) {
        float4 cv = *(const float4*)(crow + d0 + lc);
        float4 wv = *(const float4*)(wx + d0 + lc);
        cwS[(lc + 0) * 64 + lr] = cv.x * wv.x;
        cwS[(lc + 1) * 64 + lr] = cv.y * wv.y;
        cwS[(lc + 2) * 64 + lr] = cv.z * wv.z;
        cwS[(lc + 3) * 64 + lr] = cv.w * wv.w;
#pragma unroll
        for (int l = 0; l < 2; l++) {
            int j = lr + l * 64;
            float4 qv = *(const float4*)(qbase + (size_t)j * D_ + d0 + lc);
            qS[(lc + 0) * 128 + j] = qv.x;
            qS[(lc + 1) * 128 + j] = qv.y;
            qS[(lc + 2) * 128 + j] = qv.z;
            qS[(lc + 3) * 128 + j] = qv.w;
        }
        __syncthreads();
#pragma unroll
        for (int kk = 0; kk < 16; kk++) {
            float ra[4];
#pragma unroll
            for (int i = 0; i < 4; i++) ra[i] = cwS[kk * 64 + tr + i];
            float4 q0 = *(float4*)&qS[kk * 128 + tc];
            float4 q1 = *(float4*)&qS[kk * 128 + tc + 4];
            float rb[8] = {q0.x, q0.y, q0.z, q0.w, q1.x, q1.y, q1.z, q1.w};
#pragma unroll
            for (int i = 0; i < 4; i++)
#pragma unroll
                for (int j = 0; j < 8; j++) acc[i][j] += ra[i] * rb[j];
        }
        __syncthreads();
    }

    float bs = bsim[0];
#pragma unroll
    for (int i = 0; i < 4; i++) {
        float rowadd = s_sc[tr + i] + bs;
#pragma unroll
        for (int j = 0; j < 8; j++) {
            float v = acc[i][j] + rowadd + s_sq[tc + j];
            if (s_qm[tc + j] != 0.f) v = NEGV;
            sS[(tr + i) * 128 + tc + j] = v;
        }
    }
    __syncthreads();

    int lane = t & 31, warp = t >> 5;
#pragma unroll
    for (int rr = 0; rr < 8; rr++) {
        int r = warp * 8 + rr;
        float* row = sS + r * 128;
        float v0 = row[lane], v1 = row[lane + 32], v2 = row[lane + 64], v3 = row[lane + 96];
        float m = fmaxf(fmaxf(v0, v1), fmaxf(v2, v3));
#pragma unroll
        for (int o = 16; o; o >>= 1) m = fmaxf(m, __shfl_xor_sync(0xffffffffu, m, o));
        float e0 = __expf(v0 - m), e1 = __expf(v1 - m), e2 = __expf(v2 - m), e3 = __expf(v3 - m);
        float s = e0 + e1 + e2 + e3;
#pragma unroll
        for (int o = 16; o; o >>= 1) s += __shfl_xor_sync(0xffffffffu, s, o);
        float inv = 1.f / s;
        row[lane]      = e0 * inv;
        row[lane + 32] = e1 * inv;
        row[lane + 64] = e2 * inv;
        row[lane + 96] = e3 * inv;
        if (lane == 0 && r < nrows) g_rowmax[b * LC_ + it * 64 + r] = m;
    }
    __syncthreads();

    float* qS2 = sT;
    float acc2[8][8];
#pragma unroll
    for (int i = 0; i < 8; i++)
#pragma unroll
        for (int j = 0; j < 8; j++) acc2[i][j] = 0.f;

    int tr2 = (t >> 5) * 8;
    int tc2 = (t & 31) * 8;

    for (int j0 = 0; j0 < LQ_; j0 += 8) {
#pragma unroll
        for (int l = 0; l < 2; l++) {
            int idx = t + l * 256;
            int jr  = idx >> 6;
            int nc  = (idx & 63) * 4;
            *(float4*)&qS2[jr * 256 + nc] =
                *(const float4*)(qbase + (size_t)(j0 + jr) * D_ + nc);
        }
        __syncthreads();
#pragma unroll
        for (int kk = 0; kk < 8; kk++) {
            float ra[8];
#pragma unroll
            for (int i = 0; i < 8; i++) ra[i] = sS[(tr2 + i) * 128 + j0 + kk];
            float4 q0 = *(float4*)&qS2[kk * 256 + tc2];
            float4 q1 = *(float4*)&qS2[kk * 256 + tc2 + 4];
            float rb[8] = {q0.x, q0.y, q0.z, q0.w, q1.x, q1.y, q1.z, q1.w};
#pragma unroll
            for (int i = 0; i < 8; i++)
#pragma unroll
                for (int j = 0; j < 8; j++) acc2[i][j] += ra[i] * rb[j];
        }
        __syncthreads();
    }
#pragma unroll
    for (int i = 0; i < 8; i++) {
        if (tr2 + i < nrows) {
            float* dst = g_c2q + (size_t)(off + it * 64 + tr2 + i) * D_ + tc2;
            *(float4*)dst       = make_float4(acc2[i][0], acc2[i][1], acc2[i][2], acc2[i][3]);
            *(float4*)(dst + 4) = make_float4(acc2[i][4], acc2[i][5], acc2[i][6], acc2[i][7]);
        }
    }
}

// ---------------- kernels 3a-c: q2c over ACTIVE rows ----------------
__global__ void k_q2cw() {
    __shared__ float red[256];
    int b = blockIdx.x, t = threadIdx.x;
    int nb = g_cntb[b];
    if (nb == 0) return;
    const float* rm = g_rowmax + b * LC_;

    float m = -3.4e38f;
    for (int i = t; i < nb; i += 256) m = fmaxf(m, rm[i]);
    red[t] = m; __syncthreads();
    for (int s = 128; s > 0; s >>= 1) { if (t < s) red[t] = fmaxf(red[t], red[t + s]); __syncthreads(); }
    m = red[0]; __syncthreads();

    float sum = 0.f;
    for (int i = t; i < nb; i += 256) sum += __expf(rm[i] - m);
    red[t] = sum; __syncthreads();
    for (int s = 128; s > 0; s >>= 1) { if (t < s) red[t] += red[t + s]; __syncthreads(); }
    float inv = 1.f / red[0];
    __syncthreads();
    for (int i = t; i < nb; i += 256)
        g_q2cw[b * LC_ + i] = __expf(rm[i] - m) * inv;
}

__global__ void k_q2cp(const float* __restrict__ ctx) {
    int chunk = blockIdx.x, b = blockIdx.y, t = threadIdx.x;
    int nb  = g_cntb[b];
    int off = g_offb[b];
    int i0  = chunk * 64;
    int i1  = min(i0 + 64, nb);
    const float* w = g_q2cw + b * LC_;
    float acc = 0.f;
    for (int i = i0; i < i1; i++)
        acc += w[i] * ctx[(size_t)g_rows[off + i] * D_ + t];
    g_q2cp[((size_t)b * 32 + chunk) * D_ + t] = acc;
}

__global__ void k_q2cf() {
    int b = blockIdx.x, t = threadIdx.x;
    float acc = 0.f;
#pragma unroll
    for (int c = 0; c < 32; c++)
        acc += g_q2cp[((size_t)b * 32 + c) * D_ + t];
    g_q2c[b * D_ + t] = acc;
}

// ---------------- kernel 4: zero masked output rows ----------------
__global__ void k_zero(const void* cm, float* __restrict__ out) {
    int row = blockIdx.x;
    if (maskval(cm, g_maskbyte, row) != 0.f)
        ((float4*)out)[(size_t)row * 256 + threadIdx.x] = make_float4(0.f, 0.f, 0.f, 0.f);
}

// ---------------- kernel 5: build X as bf16 hi/lo split (packed) ----------------
__global__ void k_buildX(const float* __restrict__ ctx) {
    int m = blockIdx.x;
    if (m >= g_nact) return;
    int r = g_rows[m];
    int b = r >> 11;
    int t = threadIdx.x;
    int seg = t >> 6, kk = t & 63;
    const float4* c4 = (const float4*)ctx + (size_t)r * 64;
    float4 v;
    if (seg == 0) v = c4[kk];
    else if (seg == 1) v = ((const float4*)g_c2q)[(size_t)m * 64 + kk];
    else if (seg == 2) {
        float4 a = c4[kk]; float4 q = ((const float4*)g_c2q)[(size_t)m * 64 + kk];
        v = make_float4(a.x * q.x, a.y * q.y, a.z * q.z, a.w * q.w);
    } else {
        float4 a = c4[kk]; float4 q = ((const float4*)g_q2c)[b * 64 + kk];
        v = make_float4(a.x * q.x, a.y * q.y, a.z * q.z, a.w * q.w);
    }
    float vv[4] = {v.x, v.y, v.z, v.w};
    __nv_bfloat16 h[4], l[4];
#pragma unroll
    for (int i = 0; i < 4; i++) {
        h[i] = __float2bfloat16(vv[i]);
        l[i] = __float2bfloat16(vv[i] - __bfloat162float(h[i]));
    }
    size_t offb = (size_t)m * D8_ + t * 4;
    __nv_bfloat162 h0; h0.x = h[0]; h0.y = h[1];
    __nv_bfloat162 h1; h1.x = h[2]; h1.y = h[3];
    __nv_bfloat162 l0; l0.x = l[0]; l0.y = l[1];
    __nv_bfloat162 l1; l1.x = l[2]; l1.y = l[3];
    *(__nv_bfloat162*)(g_Xh + offb)     = h0;
    *(__nv_bfloat162*)(g_Xh + offb + 2) = h1;
    *(__nv_bfloat162*)(g_Xl + offb)     = l0;
    *(__nv_bfloat162*)(g_Xl + offb + 2) = l1;
}

// ---------------- kernel 5b: transpose + bf16-split weights ----------------
__global__ void k_wconv(const float* __restrict__ Wi, const float* __restrict__ Wo) {
    __shared__ float tile[32][33];
    const float* W = blockIdx.z ? Wo : Wi;
    __nv_bfloat16* Wh = g_Wh[blockIdx.z];
    __nv_bfloat16* Wl = g_Wl[blockIdx.z];
    int k0 = blockIdx.y * 32, n0 = blockIdx.x * 32;
    int t = threadIdx.x;
    int r = t >> 5, c = t & 31;
#pragma unroll
    for (int i = 0; i < 4; i++)
        tile[r + i * 8][c] = W[(size_t)(k0 + r + i * 8) * D8_ + n0 + c];
    __syncthreads();
#pragma unroll
    for (int i = 0; i < 4; i++) {
        int n = r + i * 8;
        float v = tile[c][n];
        __nv_bfloat16 h = __float2bfloat16(v);
        size_t off = (size_t)(n0 + n) * D8_ + k0 + c;
        Wh[off] = h;
        Wl[off] = __float2bfloat16(v - __bfloat162float(h));
    }
}

// ---------------- kernel 6: mma.sync bf16x3 GEMM, 128x128 tile, BK=64, 2-stage ----------------
#define TROW    144
#define ARR_B   (128 * TROW)
#define STAGE_B (4 * ARR_B)
#define GEMM_SMEM_BYTES (2 * STAGE_B)   // 147456

template <int MODE>
__global__ __launch_bounds__(256, 1) void k_gemm_mma(
    const float* __restrict__ bias, float* __restrict__ out)
{
    extern __shared__ char smem[];
    const int M = g_nact;
    const int bm = blockIdx.y, bn = blockIdx.x;
    if (bm * 128 >= M) return;

    uint32_t sbase = smem_u32(smem);

    int t = threadIdx.x;
    int wid = t >> 5, lane = t & 31;
    int warp_m = wid >> 2;
    int warp_n = wid & 3;

    const __nv_bfloat16* AhG = (MODE == 0) ? g_Xh : g_Hh;
    const __nv_bfloat16* AlG = (MODE == 0) ? g_Xl : g_Hl;
    const __nv_bfloat16* BhG = g_Wh[MODE];
    const __nv_bfloat16* BlG = g_Wl[MODE];

    int lrow  = t >> 1;
    int lcolb = (t & 1) * 32;
    int arow  = bm * 128 + lrow;
    if (arow >= M) arow = M - 1;
    const __nv_bfloat16* gAh = AhG + (size_t)arow * D8_ + lcolb;
    const __nv_bfloat16* gAl = AlG + (size_t)arow * D8_ + lcolb;
    const __nv_bfloat16* gBh = BhG + (size_t)(bn * 128 + lrow) * D8_ + lcolb;
    const __nv_bfloat16* gBl = BlG + (size_t)(bn * 128 + lrow) * D8_ + lcolb;
    uint32_t s_off = lrow * TROW + lcolb * 2;

#define LOAD_CHUNK(k0, stg) do { \
    uint32_t sb = sbase + (stg) * STAGE_B + s_off; \
    _Pragma("unroll") \
    for (int j = 0; j < 4; j++) { \
        CP16(sb + 0 * ARR_B + j * 16, gAh + (k0) + j * 8); \
        CP16(sb + 1 * ARR_B + j * 16, gAl + (k0) + j * 8); \
        CP16(sb + 2 * ARR_B + j * 16, gBh + (k0) + j * 8); \
        CP16(sb + 3 * ARR_B + j * 16, gBl + (k0) + j * 8); \
    } \
    CP_COMMIT(); \
} while (0)

    float acc[4][4][4];
#pragma unroll
    for (int mi = 0; mi < 4; mi++)
#pragma unroll
        for (int ni = 0; ni < 4; ni++)
#pragma unroll
            for (int k = 0; k < 4; k++) acc[mi][ni][k] = 0.f;

    uint32_t aAddrBase = (warp_m * 64 + (lane & 15)) * TROW + ((lane >> 4) & 1) * 16;
    uint32_t bAddrBase = 2 * ARR_B + (warp_n * 32 + (lane & 7)) * TROW + ((lane >> 3) & 1) * 16;

    LOAD_CHUNK(0, 0);

    for (int chunk = 0; chunk < 16; chunk++) {
        int buf = chunk & 1;
        if (chunk + 1 < 16) {
            LOAD_CHUNK((chunk + 1) * 64, buf ^ 1);
            CP_WAIT(1);
        } else {
            CP_WAIT(0);
        }
        __syncthreads();

        uint32_t st = sbase + buf * STAGE_B;
#pragma unroll
        for (int kk = 0; kk < 4; kk++) {
            uint32_t bh[4][2], bl[4][2];
            uint32_t bAddr = st + bAddrBase + kk * 32;
#pragma unroll
            for (int ni = 0; ni < 4; ni++) {
                LDSM_X2(bh[ni][0], bh[ni][1], bAddr + ni * 8 * TROW);
                LDSM_X2(bl[ni][0], bl[ni][1], bAddr + ni * 8 * TROW + ARR_B);
            }
#pragma unroll
            for (int mi = 0; mi < 4; mi++) {
                uint32_t aAddr = st + aAddrBase + mi * 16 * TROW + kk * 32;
                uint32_t ah[4], al[4];
                LDSM_X4(ah[0], ah[1], ah[2], ah[3], aAddr);
                LDSM_X4(al[0], al[1], al[2], al[3], aAddr + ARR_B);
#pragma unroll
                for (int ni = 0; ni < 4; ni++) {
                    MMA16816(acc[mi][ni], ah, bh[ni]);
                    MMA16816(acc[mi][ni], ah, bl[ni]);
                    MMA16816(acc[mi][ni], al, bh[ni]);
                }
            }
        }
        __syncthreads();
    }
#undef LOAD_CHUNK

    int q   = lane >> 2;
    int cp2 = (lane & 3) * 2;
#pragma unroll
    for (int ni = 0; ni < 4; ni++) {
        int col = bn * 128 + warp_n * 32 + ni * 8 + cp2;
        float bv0 = bias[col], bv1 = bias[col + 1];
#pragma unroll
        for (int mi = 0; mi < 4; mi++) {
#pragma unroll
            for (int h = 0; h < 2; h++) {
                int lm   = warp_m * 64 + mi * 16 + q + h * 8;
                int grow = bm * 128 + lm;
                if (grow < M) {
                    float v0 = acc[mi][ni][h * 2 + 0] + bv0;
                    float v1 = acc[mi][ni][h * 2 + 1] + bv1;
                    if (MODE == 0) {
                        v0 = fmaxf(v0, 0.f); v1 = fmaxf(v1, 0.f);
                        __nv_bfloat16 h0 = __float2bfloat16(v0);
                        __nv_bfloat16 h1 = __float2bfloat16(v1);
                        __nv_bfloat162 hh; hh.x = h0; hh.y = h1;
                        __nv_bfloat162 ll;
                        ll.x = __float2bfloat16(v0 - __bfloat162float(h0));
                        ll.y = __float2bfloat16(v1 - __bfloat162float(h1));
                        size_t off = (size_t)grow * D8_ + col;
                        *(__nv_bfloat162*)(g_Hh + off) = hh;
                        *(__nv_bfloat162*)(g_Hl + off) = ll;
                    } else {
                        float2 vv; vv.x = v0; vv.y = v1;
                        *(float2*)(out + (size_t)g_rows[grow] * D8_ + col) = vv;
                    }
                }
            }
        }
    }
}

// ---------------- launch (fork/join streams inside graph capture) ----------------
extern "C" void kernel_launch(void* const* d_in, const int* in_sizes, int n_in,
                              void* d_out, int out_size) {
    const float* ctx  = (const float*)d_in[0];
    const void*  cm   = d_in[1];
    const float* qry  = (const float*)d_in[2];
    const void*  qm   = d_in[3];
    const float* wsim = (const float*)d_in[4];
    const float* bsim = (const float*)d_in[5];
    const float* wi   = (const float*)d_in[6];
    const float* bi   = (const float*)d_in[7];
    const float* wo   = (const float*)d_in[8];
    const float* bo   = (const float*)d_in[9];
    float* out = (float*)d_out;

    static cudaStream_t sSide = nullptr, sZero = nullptr;
    static cudaEvent_t evFork = nullptr, evSide = nullptr, evDet = nullptr, evZero = nullptr;
    if (sSide == nullptr) {
        cudaStreamCreateWithFlags(&sSide, cudaStreamNonBlocking);
        cudaStreamCreateWithFlags(&sZero, cudaStreamNonBlocking);
        cudaEventCreateWithFlags(&evFork, cudaEventDisableTiming);
        cudaEventCreateWithFlags(&evSide, cudaEventDisableTiming);
        cudaEventCreateWithFlags(&evDet,  cudaEventDisableTiming);
        cudaEventCreateWithFlags(&evZero, cudaEventDisableTiming);
        cudaFuncSetAttribute(k_gemm_mma<0>, cudaFuncAttributeMaxDynamicSharedMemorySize, GEMM_SMEM_BYTES);
        cudaFuncSetAttribute(k_gemm_mma<1>, cudaFuncAttributeMaxDynamicSharedMemorySize, GEMM_SMEM_BYTES);
    }

    // fork: side stream does scsq (no mask dep) + wconv (fully independent)
    cudaEventRecord(evFork, 0);
    cudaStreamWaitEvent(sSide, evFork, 0);
    k_scsq<<<(NROWS + B_ * LQ_) / 8, 256, 0, sSide>>>(ctx, qry, wsim);
    k_wconv<<<dim3(32, 32, 2), 256, 0, sSide>>>(wi, wo);
    cudaEventRecord(evSide, sSide);

    // main: mask prolog chain; k_zero overlapped on its own stream
    k_detect<<<1, 256>>>((const unsigned int*)cm);
    cudaEventRecord(evDet, 0);
    cudaStreamWaitEvent(sZero, evDet, 0);
    k_zero<<<NROWS, 256, 0, sZero>>>(cm, out);
    cudaEventRecord(evZero, sZero);

    k_count<<<B_, 256>>>(cm);
    k_off<<<1, 32>>>();
    k_fill<<<B_, 256>>>(cm);

    // join side (attn needs g_sc/g_sq; gemm0 needs W converted)
    cudaStreamWaitEvent(0, evSide, 0);
    k_attn<<<dim3(32, B_), 256>>>(ctx, qry, qm, wsim, bsim);
    k_q2cw<<<B_, 256>>>();
    k_q2cp<<<dim3(32, B_), 256>>>(ctx);
    k_q2cf<<<B_, 256>>>();
    k_buildX<<<NROWS, 256>>>(ctx);
    k_gemm_mma<0><<<dim3(8, NROWS / 128), 256, GEMM_SMEM_BYTES>>>(bi, nullptr);
    cudaStreamWaitEvent(0, evZero, 0);
    k_gemm_mma<1><<<dim3(8, NROWS / 128), 256, GEMM_SMEM_BYTES>>>(bo, out);
}

// round 17
// speedup vs baseline: 1.0581x; 1.0037x over previous
#include <cuda_runtime.h>
#include <cuda_bf16.h>
#include <cstdint>
#include <cstddef>

#define B_     8
#define LC_    2048
#define LQ_    128
#define D_     256
#define D8_    1024
#define NROWS  16384
#define NEGV   (-10000000000.0f)

// ================= scratch (static device globals; no allocation) =================
__device__ float g_sc[NROWS];
__device__ float g_sq[B_ * LQ_];
__device__ float g_rowmax[NROWS];
__device__ float g_c2q[NROWS * D_];
__device__ float g_q2c[B_ * D_];
__device__ float g_q2cw[B_ * LC_];
__device__ float g_q2cp[B_ * 32 * D_];
__device__ int   g_rows[NROWS];
__device__ int   g_cntb[B_];
__device__ int   g_offb[B_ + 1];
__device__ int   g_nact;
__device__ int   g_maskbyte;
__device__ int   g_tilectr;
__device__ int   g_done[128];
__device__ __nv_bfloat16 g_Xh[(size_t)NROWS * D8_];
__device__ __nv_bfloat16 g_Xl[(size_t)NROWS * D8_];
__device__ __nv_bfloat16 g_Hh[(size_t)NROWS * D8_];
__device__ __nv_bfloat16 g_Hl[(size_t)NROWS * D8_];
__device__ __nv_bfloat16 g_Wh[2][(size_t)D8_ * D8_];
__device__ __nv_bfloat16 g_Wl[2][(size_t)D8_ * D8_];

__device__ __forceinline__ float maskval(const void* p, int mb, int i) {
    return mb ? (float)((const unsigned char*)p)[i]
              : (float)((const int*)p)[i];
}

__device__ __forceinline__ uint32_t smem_u32(const void* smem_ptr) {
    uint32_t addr;
    asm("{ .reg .u64 tmp; cvta.to.shared.u64 tmp, %1; cvt.u32.u64 %0, tmp; }"
        : "=r"(addr) : "l"(smem_ptr));
    return addr;
}

#define CP16(s, g) asm volatile("cp.async.ca.shared.global [%0], [%1], 16;" :: "r"(s), "l"(g))
#define CP_COMMIT() asm volatile("cp.async.commit_group;" ::: "memory")
#define CP_WAIT(n)  asm volatile("cp.async.wait_group %0;" :: "n"(n) : "memory")

#define LDSM_X4(r0,r1,r2,r3, addr) \
    asm volatile("ldmatrix.sync.aligned.m8n8.x4.shared.b16 {%0,%1,%2,%3}, [%4];" \
        : "=r"(r0),"=r"(r1),"=r"(r2),"=r"(r3) : "r"(addr))
#define LDSM_X2(r0,r1, addr) \
    asm volatile("ldmatrix.sync.aligned.m8n8.x2.shared.b16 {%0,%1}, [%2];" \
        : "=r"(r0),"=r"(r1) : "r"(addr))

#define MMA16816(c, a, b) \
    asm volatile("mma.sync.aligned.m16n8k16.row.col.f32.bf16.bf16.f32 " \
        "{%0,%1,%2,%3}, {%4,%5,%6,%7}, {%8,%9}, {%0,%1,%2,%3};" \
        : "+f"((c)[0]),"+f"((c)[1]),"+f"((c)[2]),"+f"((c)[3]) \
        : "r"((a)[0]),"r"((a)[1]),"r"((a)[2]),"r"((a)[3]), "r"((b)[0]),"r"((b)[1]))

// ---------------- kernel 0: detect mask dtype ----------------
__global__ void k_detect(const unsigned int* cm) {
    __shared__ int f;
    if (threadIdx.x == 0) f = 0;
    __syncthreads();
    int any = 0;
    for (int i = threadIdx.x; i < NROWS / 4; i += blockDim.x)
        any |= (cm[i] > 1u) ? 1 : 0;
    if (any) atomicOr(&f, 1);
    __syncthreads();
    if (threadIdx.x == 0) g_maskbyte = f;
}

// ---------------- kernel 0b: per-batch active counts ----------------
__global__ void k_count(const void* cm) {
    __shared__ int red[256];
    int b = blockIdx.x, t = threadIdx.x;
    int mb = g_maskbyte;
    int cnt = 0;
    for (int i = t; i < LC_; i += 256)
        cnt += (maskval(cm, mb, b * LC_ + i) == 0.f) ? 1 : 0;
    red[t] = cnt; __syncthreads();
    for (int s = 128; s > 0; s >>= 1) { if (t < s) red[t] += red[t + s]; __syncthreads(); }
    if (t == 0) g_cntb[b] = red[0];
}

// ---------------- kernel 0c: prefix offsets + reset GEMM scheduler state ----------------
__global__ void k_off() {
    int t = threadIdx.x;
    if (t < 128) g_done[t] = 0;
    if (t == 0) {
        g_tilectr = 0;
        int s = 0;
        for (int b = 0; b < B_; b++) { g_offb[b] = s; s += g_cntb[b]; }
        g_offb[B_] = s;
        g_nact = s;
    }
}

// ---------------- kernel 0d: deterministic packed fill (ballot scan) ----------------
__global__ void k_fill(const void* cm) {
    __shared__ int warpsums[8];
    int b = blockIdx.x, t = threadIdx.x;
    int lane = t & 31, wid = t >> 5;
    int mb = g_maskbyte;
    int base = g_offb[b];
    int running = 0;
    for (int g = 0; g < LC_ / 256; g++) {
        int row = b * LC_ + g * 256 + t;
        int a = (maskval(cm, mb, row) == 0.f) ? 1 : 0;
        unsigned bal = __ballot_sync(0xffffffffu, a);
        int rank = __popc(bal & ((1u << lane) - 1));
        if (lane == 0) warpsums[wid] = __popc(bal);
        __syncthreads();
        int wbase = 0, tot = 0;
#pragma unroll
        for (int w = 0; w < 8; w++) {
            int ws = warpsums[w];
            if (w < wid) wbase += ws;
            tot += ws;
        }
        if (a) g_rows[base + running + wbase + rank] = row;
        running += tot;
        __syncthreads();
    }
}

// ---------------- kernel 1: sc/sq matvecs ----------------
__global__ void k_scsq(const float* __restrict__ ctx, const float* __restrict__ qry,
                       const float* __restrict__ wsim) {
    int gw   = (blockIdx.x * blockDim.x + threadIdx.x) >> 5;
    int lane = threadIdx.x & 31;
    if (gw < NROWS) {
        const float* p = ctx + (size_t)gw * D_;
        float s = 0.f;
#pragma unroll
        for (int q = 0; q < 8; q++) { int d = lane + 32 * q; s += p[d] * wsim[d]; }
#pragma unroll
        for (int o = 16; o; o >>= 1) s += __shfl_xor_sync(0xffffffffu, s, o);
        if (lane == 0) g_sc[gw] = s;
    } else if (gw < NROWS + B_ * LQ_) {
        int w2 = gw - NROWS;
        const float* p = qry + (size_t)w2 * D_;
        float s = 0.f;
#pragma unroll
        for (int q = 0; q < 8; q++) { int d = lane + 32 * q; s += p[d] * wsim[D_ + d]; }
#pragma unroll
        for (int o = 16; o; o >>= 1) s += __shfl_xor_sync(0xffffffffu, s, o);
        if (lane == 0) g_sq[w2] = s;
    }
}

// ---------------- kernel 2: fused sim + softmax + c2q + rowmax (ACTIVE rows only) ----------------
__global__ __launch_bounds__(256) void k_attn(
    const float* __restrict__ ctx, const float* __restrict__ qry,
    const void* qm_,
    const float* __restrict__ wsim, const float* __restrict__ bsim)
{
    __shared__ float sS[64 * 128];
    __shared__ float sT[3072];
    __shared__ float s_sc[64], s_sq[128], s_qm[128];
    __shared__ int   s_ridx[64];

    int t  = threadIdx.x;
    int b  = blockIdx.y;
    int it = blockIdx.x;
    int nb = g_cntb[b];
    if (it * 64 >= nb) return;
    int off    = g_offb[b];
    int nrows  = min(64, nb - it * 64);
    int mb     = g_maskbyte;

    if (t < 64) {
        int li = it * 64 + t;
        int r  = g_rows[off + (t < nrows ? li : it * 64)];
        s_ridx[t] = r;
        s_sc[t]   = g_sc[r];
    } else if (t < 192) {
        int j = t - 64;
        s_sq[j] = g_sq[b * LQ_ + j];
        s_qm[j] = maskval(qm_, mb, b * LQ_ + j);
    }
    __syncthreads();

    float* cwS = sT;
    float* qS  = sT + 1024;
    const float* wx    = wsim + 2 * D_;
    const float* qbase = qry + (size_t)b * LQ_ * D_;

    float acc[4][8];
#pragma unroll
    for (int i = 0; i < 4; i++)
#pragma unroll
        for (int j = 0; j < 8; j++) acc[i][j] = 0.f;

    int tr = (t >> 4) * 4;
    int tc = (t & 15) * 8;
    int lr = t >> 2;
    int lc = (t & 3) * 4;
    const float* crow = ctx + (size_t)s_ridx[lr] * D_;

    for (int d0 = 0; d0 < D_; d0 += 16) {
        float4 cv = *(const float4*)(crow + d0 + lc);
        float4 wv = *(const float4*)(wx + d0 + lc);
        cwS[(lc + 0) * 64 + lr] = cv.x * wv.x;
        cwS[(lc + 1) * 64 + lr] = cv.y * wv.y;
        cwS[(lc + 2) * 64 + lr] = cv.z * wv.z;
        cwS[(lc + 3) * 64 + lr] = cv.w * wv.w;
#pragma unroll
        for (int l = 0; l < 2; l++) {
            int j = lr + l * 64;
            float4 qv = *(const float4*)(qbase + (size_t)j * D_ + d0 + lc);
            qS[(lc + 0) * 128 + j] = qv.x;
            qS[(lc + 1) * 128 + j] = qv.y;
            qS[(lc + 2) * 128 + j] = qv.z;
            qS[(lc + 3) * 128 + j] = qv.w;
        }
        __syncthreads();
#pragma unroll
        for (int kk = 0; kk < 16; kk++) {
            float ra[4];
#pragma unroll
            for (int i = 0; i < 4; i++) ra[i] = cwS[kk * 64 + tr + i];
            float4 q0 = *(float4*)&qS[kk * 128 + tc];
            float4 q1 = *(float4*)&qS[kk * 128 + tc + 4];
            float rb[8] = {q0.x, q0.y, q0.z, q0.w, q1.x, q1.y, q1.z, q1.w};
#pragma unroll
            for (int i = 0; i < 4; i++)
#pragma unroll
                for (int j = 0; j < 8; j++) acc[i][j] += ra[i] * rb[j];
        }
        __syncthreads();
    }

    float bs = bsim[0];
#pragma unroll
    for (int i = 0; i < 4; i++) {
        float rowadd = s_sc[tr + i] + bs;
#pragma unroll
        for (int j = 0; j < 8; j++) {
            float v = acc[i][j] + rowadd + s_sq[tc + j];
            if (s_qm[tc + j] != 0.f) v = NEGV;
            sS[(tr + i) * 128 + tc + j] = v;
        }
    }
    __syncthreads();

    int lane = t & 31, warp = t >> 5;
#pragma unroll
    for (int rr = 0; rr < 8; rr++) {
        int r = warp * 8 + rr;
        float* row = sS + r * 128;
        float v0 = row[lane], v1 = row[lane + 32], v2 = row[lane + 64], v3 = row[lane + 96];
        float m = fmaxf(fmaxf(v0, v1), fmaxf(v2, v3));
#pragma unroll
        for (int o = 16; o; o >>= 1) m = fmaxf(m, __shfl_xor_sync(0xffffffffu, m, o));
        float e0 = __expf(v0 - m), e1 = __expf(v1 - m), e2 = __expf(v2 - m), e3 = __expf(v3 - m);
        float s = e0 + e1 + e2 + e3;
#pragma unroll
        for (int o = 16; o; o >>= 1) s += __shfl_xor_sync(0xffffffffu, s, o);
        float inv = 1.f / s;
        row[lane]      = e0 * inv;
        row[lane + 32] = e1 * inv;
        row[lane + 64] = e2 * inv;
        row[lane + 96] = e3 * inv;
        if (lane == 0 && r < nrows) g_rowmax[b * LC_ + it * 64 + r] = m;
    }
    __syncthreads();

    float* qS2 = sT;
    float acc2[8][8];
#pragma unroll
    for (int i = 0; i < 8; i++)
#pragma unroll
        for (int j = 0; j < 8; j++) acc2[i][j] = 0.f;

    int tr2 = (t >> 5) * 8;
    int tc2 = (t & 31) * 8;

    for (int j0 = 0; j0 < LQ_; j0 += 8) {
#pragma unroll
        for (int l = 0; l < 2; l++) {
            int idx = t + l * 256;
            int jr  = idx >> 6;
            int nc  = (idx & 63) * 4;
            *(float4*)&qS2[jr * 256 + nc] =
                *(const float4*)(qbase + (size_t)(j0 + jr) * D_ + nc);
        }
        __syncthreads();
#pragma unroll
        for (int kk = 0; kk < 8; kk++) {
            float ra[8];
#pragma unroll
            for (int i = 0; i < 8; i++) ra[i] = sS[(tr2 + i) * 128 + j0 + kk];
            float4 q0 = *(float4*)&qS2[kk * 256 + tc2];
            float4 q1 = *(float4*)&qS2[kk * 256 + tc2 + 4];
            float rb[8] = {q0.x, q0.y, q0.z, q0.w, q1.x, q1.y, q1.z, q1.w};
#pragma unroll
            for (int i = 0; i < 8; i++)
#pragma unroll
                for (int j = 0; j < 8; j++) acc2[i][j] += ra[i] * rb[j];
        }
        __syncthreads();
    }
#pragma unroll
    for (int i = 0; i < 8; i++) {
        if (tr2 + i < nrows) {
            float* dst = g_c2q + (size_t)(off + it * 64 + tr2 + i) * D_ + tc2;
            *(float4*)dst       = make_float4(acc2[i][0], acc2[i][1], acc2[i][2], acc2[i][3]);
            *(float4*)(dst + 4) = make_float4(acc2[i][4], acc2[i][5], acc2[i][6], acc2[i][7]);
        }
    }
}

// ---------------- kernels 3a-c: q2c over ACTIVE rows ----------------
__global__ void k_q2cw() {
    __shared__ float red[256];
    int b = blockIdx.x, t = threadIdx.x;
    int nb = g_cntb[b];
    if (nb == 0) return;
    const float* rm = g_rowmax + b * LC_;

    float m = -3.4e38f;
    for (int i = t; i < nb; i += 256) m = fmaxf(m, rm[i]);
    red[t] = m; __syncthreads();
    for (int s = 128; s > 0; s >>= 1) { if (t < s) red[t] = fmaxf(red[t], red[t + s]); __syncthreads(); }
    m = red[0]; __syncthreads();

    float sum = 0.f;
    for (int i = t; i < nb; i += 256) sum += __expf(rm[i] - m);
    red[t] = sum; __syncthreads();
    for (int s = 128; s > 0; s >>= 1) { if (t < s) red[t] += red[t + s]; __syncthreads(); }
    float inv = 1.f / red[0];
    __syncthreads();
    for (int i = t; i < nb; i += 256)
        g_q2cw[b * LC_ + i] = __expf(rm[i] - m) * inv;
}

__global__ void k_q2cp(const float* __restrict__ ctx) {
    int chunk = blockIdx.x, b = blockIdx.y, t = threadIdx.x;
    int nb  = g_cntb[b];
    int off = g_offb[b];
    int i0  = chunk * 64;
    int i1  = min(i0 + 64, nb);
    const float* w = g_q2cw + b * LC_;
    float acc = 0.f;
    for (int i = i0; i < i1; i++)
        acc += w[i] * ctx[(size_t)g_rows[off + i] * D_ + t];
    g_q2cp[((size_t)b * 32 + chunk) * D_ + t] = acc;
}

__global__ void k_q2cf() {
    int b = blockIdx.x, t = threadIdx.x;
    float acc = 0.f;
#pragma unroll
    for (int c = 0; c < 32; c++)
        acc += g_q2cp[((size_t)b * 32 + c) * D_ + t];
    g_q2c[b * D_ + t] = acc;
}

// ---------------- kernel 4: zero masked output rows ----------------
__global__ void k_zero(const void* cm, float* __restrict__ out) {
    int row = blockIdx.x;
    if (maskval(cm, g_maskbyte, row) != 0.f)
        ((float4*)out)[(size_t)row * 256 + threadIdx.x] = make_float4(0.f, 0.f, 0.f, 0.f);
}

// ---------------- kernel 5: build X as bf16 hi/lo split (packed) ----------------
__global__ void k_buildX(const float* __restrict__ ctx) {
    int m = blockIdx.x;
    if (m >= g_nact) return;
    int r = g_rows[m];
    int b = r >> 11;
    int t = threadIdx.x;
    int seg = t >> 6, kk = t & 63;
    const float4* c4 = (const float4*)ctx + (size_t)r * 64;
    float4 v;
    if (seg == 0) v = c4[kk];
    else if (seg == 1) v = ((const float4*)g_c2q)[(size_t)m * 64 + kk];
    else if (seg == 2) {
        float4 a = c4[kk]; float4 q = ((const float4*)g_c2q)[(size_t)m * 64 + kk];
        v = make_float4(a.x * q.x, a.y * q.y, a.z * q.z, a.w * q.w);
    } else {
        float4 a = c4[kk]; float4 q = ((const float4*)g_q2c)[b * 64 + kk];
        v = make_float4(a.x * q.x, a.y * q.y, a.z * q.z, a.w * q.w);
    }
    float vv[4] = {v.x, v.y, v.z, v.w};
    __nv_bfloat16 h[4], l[4];
#pragma unroll
    for (int i = 0; i < 4; i++) {
        h[i] = __float2bfloat16(vv[i]);
        l[i] = __float2bfloat16(vv[i] - __bfloat162float(h[i]));
    }
    size_t offb = (size_t)m * D8_ + t * 4;
    __nv_bfloat162 h0; h0.x = h[0]; h0.y = h[1];
    __nv_bfloat162 h1; h1.x = h[2]; h1.y = h[3];
    __nv_bfloat162 l0; l0.x = l[0]; l0.y = l[1];
    __nv_bfloat162 l1; l1.x = l[2]; l1.y = l[3];
    *(__nv_bfloat162*)(g_Xh + offb)     = h0;
    *(__nv_bfloat162*)(g_Xh + offb + 2) = h1;
    *(__nv_bfloat162*)(g_Xl + offb)     = l0;
    *(__nv_bfloat162*)(g_Xl + offb + 2) = l1;
}

// ---------------- kernel 5b: transpose + bf16-split weights ----------------
__global__ void k_wconv(const float* __restrict__ Wi, const float* __restrict__ Wo) {
    __shared__ float tile[32][33];
    const float* W = blockIdx.z ? Wo : Wi;
    __nv_bfloat16* Wh = g_Wh[blockIdx.z];
    __nv_bfloat16* Wl = g_Wl[blockIdx.z];
    int k0 = blockIdx.y * 32, n0 = blockIdx.x * 32;
    int t = threadIdx.x;
    int r = t >> 5, c = t & 31;
#pragma unroll
    for (int i = 0; i < 4; i++)
        tile[r + i * 8][c] = W[(size_t)(k0 + r + i * 8) * D8_ + n0 + c];
    __syncthreads();
#pragma unroll
    for (int i = 0; i < 4; i++) {
        int n = r + i * 8;
        float v = tile[c][n];
        __nv_bfloat16 h = __float2bfloat16(v);
        size_t off = (size_t)(n0 + n) * D8_ + k0 + c;
        Wh[off] = h;
        Wl[off] = __float2bfloat16(v - __bfloat162float(h));
    }
}

// ---------------- kernel 6: FUSED persistent bf16x3 GEMM pair ----------------
// Tiles [0, ntiles) = GEMM0 (H = relu(X@Wi+bi)); [ntiles, 2*ntiles) = GEMM1
// (out = H@Wo+bo, scatter). GEMM1 tile (bm,·) waits on g_done[bm]==8.
#define TROW    144
#define ARR_B   (128 * TROW)
#define STAGE_B (4 * ARR_B)
#define GEMM_SMEM_BYTES (2 * STAGE_B)   // 147456
#define GEMM_GRID 148

__global__ __launch_bounds__(256, 1) void k_gemm_fused(
    const float* __restrict__ bi, const float* __restrict__ bo,
    float* __restrict__ out)
{
    extern __shared__ char smem[];
    __shared__ int s_tid;
    const int M = g_nact;
    const int nbm = (M + 127) >> 7;
    const int ntiles = nbm * 8;

    uint32_t sbase = smem_u32(smem);
    int t = threadIdx.x;
    int wid = t >> 5, lane = t & 31;
    int warp_m = wid >> 2;
    int warp_n = wid & 3;
    int lrow  = t >> 1;
    int lcolb = (t & 1) * 32;
    uint32_t s_off = lrow * TROW + lcolb * 2;
    uint32_t aAddrBase = (warp_m * 64 + (lane & 15)) * TROW + ((lane >> 4) & 1) * 16;
    uint32_t bAddrBase = 2 * ARR_B + (warp_n * 32 + (lane & 7)) * TROW + ((lane >> 3) & 1) * 16;
    int q   = lane >> 2;
    int cp2 = (lane & 3) * 2;

    for (;;) {
        if (t == 0) s_tid = atomicAdd(&g_tilectr, 1);
        __syncthreads();
        int tid = s_tid;
        __syncthreads();                 // s_tid consumed before next overwrite
        if (tid >= 2 * ntiles) break;

        int mode = (tid >= ntiles) ? 1 : 0;
        int lt = mode ? tid - ntiles : tid;
        int bm = lt >> 3, bn = lt & 7;

        if (mode == 1) {
            // acquire: wait for all 8 GEMM0 tiles of row-block bm
            if (t == 0) {
                while (((volatile int*)g_done)[bm] < 8) __nanosleep(64);
                __threadfence();
            }
            __syncthreads();
        }

        const __nv_bfloat16* AhG = (mode == 0) ? g_Xh : g_Hh;
        const __nv_bfloat16* AlG = (mode == 0) ? g_Xl : g_Hl;
        const __nv_bfloat16* BhG = g_Wh[mode];
        const __nv_bfloat16* BlG = g_Wl[mode];
        const float* bias = (mode == 0) ? bi : bo;

        int arow = bm * 128 + lrow;
        if (arow >= M) arow = M - 1;
        const __nv_bfloat16* gAh = AhG + (size_t)arow * D8_ + lcolb;
        const __nv_bfloat16* gAl = AlG + (size_t)arow * D8_ + lcolb;
        const __nv_bfloat16* gBh = BhG + (size_t)(bn * 128 + lrow) * D8_ + lcolb;
        const __nv_bfloat16* gBl = BlG + (size_t)(bn * 128 + lrow) * D8_ + lcolb;

#define LOAD_CHUNK(k0, stg) do { \
    uint32_t sb = sbase + (stg) * STAGE_B + s_off; \
    _Pragma("unroll") \
    for (int j = 0; j < 4; j++) { \
        CP16(sb + 0 * ARR_B + j * 16, gAh + (k0) + j * 8); \
        CP16(sb + 1 * ARR_B + j * 16, gAl + (k0) + j * 8); \
        CP16(sb + 2 * ARR_B + j * 16, gBh + (k0) + j * 8); \
        CP16(sb + 3 * ARR_B + j * 16, gBl + (k0) + j * 8); \
    } \
    CP_COMMIT(); \
} while (0)

        float acc[4][4][4];
#pragma unroll
        for (int mi = 0; mi < 4; mi++)
#pragma unroll
            for (int ni = 0; ni < 4; ni++)
#pragma unroll
                for (int k = 0; k < 4; k++) acc[mi][ni][k] = 0.f;

        LOAD_CHUNK(0, 0);

        for (int chunk = 0; chunk < 16; chunk++) {
            int buf = chunk & 1;
            if (chunk + 1 < 16) {
                LOAD_CHUNK((chunk + 1) * 64, buf ^ 1);
                CP_WAIT(1);
            } else {
                CP_WAIT(0);
            }
            __syncthreads();

            uint32_t st = sbase + buf * STAGE_B;
#pragma unroll
            for (int kk = 0; kk < 4; kk++) {
                uint32_t bh[4][2], bl[4][2];
                uint32_t bAddr = st + bAddrBase + kk * 32;
#pragma unroll
                for (int ni = 0; ni < 4; ni++) {
                    LDSM_X2(bh[ni][0], bh[ni][1], bAddr + ni * 8 * TROW);
                    LDSM_X2(bl[ni][0], bl[ni][1], bAddr + ni * 8 * TROW + ARR_B);
                }
#pragma unroll
                for (int mi = 0; mi < 4; mi++) {
                    uint32_t aAddr = st + aAddrBase + mi * 16 * TROW + kk * 32;
                    uint32_t ah[4], al[4];
                    LDSM_X4(ah[0], ah[1], ah[2], ah[3], aAddr);
                    LDSM_X4(al[0], al[1], al[2], al[3], aAddr + ARR_B);
#pragma unroll
                    for (int ni = 0; ni < 4; ni++) {
                        MMA16816(acc[mi][ni], ah, bh[ni]);
                        MMA16816(acc[mi][ni], ah, bl[ni]);
                        MMA16816(acc[mi][ni], al, bh[ni]);
                    }
                }
            }
            __syncthreads();
        }
#undef LOAD_CHUNK

#pragma unroll
        for (int ni = 0; ni < 4; ni++) {
            int col = bn * 128 + warp_n * 32 + ni * 8 + cp2;
            float bv0 = bias[col], bv1 = bias[col + 1];
#pragma unroll
            for (int mi = 0; mi < 4; mi++) {
#pragma unroll
                for (int h = 0; h < 2; h++) {
                    int lm   = warp_m * 64 + mi * 16 + q + h * 8;
                    int grow = bm * 128 + lm;
                    if (grow < M) {
                        float v0 = acc[mi][ni][h * 2 + 0] + bv0;
                        float v1 = acc[mi][ni][h * 2 + 1] + bv1;
                        if (mode == 0) {
                            v0 = fmaxf(v0, 0.f); v1 = fmaxf(v1, 0.f);
                            __nv_bfloat16 h0 = __float2bfloat16(v0);
                            __nv_bfloat16 h1 = __float2bfloat16(v1);
                            __nv_bfloat162 hh; hh.x = h0; hh.y = h1;
                            __nv_bfloat162 ll;
                            ll.x = __float2bfloat16(v0 - __bfloat162float(h0));
                            ll.y = __float2bfloat16(v1 - __bfloat162float(h1));
                            size_t off = (size_t)grow * D8_ + col;
                            *(__nv_bfloat162*)(g_Hh + off) = hh;
                            *(__nv_bfloat162*)(g_Hl + off) = ll;
                        } else {
                            float2 vv; vv.x = v0; vv.y = v1;
                            *(float2*)(out + (size_t)g_rows[grow] * D8_ + col) = vv;
                        }
                    }
                }
            }
        }

        if (mode == 0) {
            // release: make H visible, then signal row-block completion
            __threadfence();
            __syncthreads();
            if (t == 0) atomicAdd(&g_done[bm], 1);
        }
        __syncthreads();   // smem reuse safe for next tile
    }
}

// ---------------- launch (fork/join streams inside graph capture) ----------------
extern "C" void kernel_launch(void* const* d_in, const int* in_sizes, int n_in,
                              void* d_out, int out_size) {
    const float* ctx  = (const float*)d_in[0];
    const void*  cm   = d_in[1];
    const float* qry  = (const float*)d_in[2];
    const void*  qm   = d_in[3];
    const float* wsim = (const float*)d_in[4];
    const float* bsim = (const float*)d_in[5];
    const float* wi   = (const float*)d_in[6];
    const float* bi   = (const float*)d_in[7];
    const float* wo   = (const float*)d_in[8];
    const float* bo   = (const float*)d_in[9];
    float* out = (float*)d_out;

    static cudaStream_t sSide = nullptr, sZero = nullptr;
    static cudaEvent_t evFork = nullptr, evSide = nullptr, evDet = nullptr, evZero = nullptr;
    if (sSide == nullptr) {
        cudaStreamCreateWithFlags(&sSide, cudaStreamNonBlocking);
        cudaStreamCreateWithFlags(&sZero, cudaStreamNonBlocking);
        cudaEventCreateWithFlags(&evFork, cudaEventDisableTiming);
        cudaEventCreateWithFlags(&evSide, cudaEventDisableTiming);
        cudaEventCreateWithFlags(&evDet,  cudaEventDisableTiming);
        cudaEventCreateWithFlags(&evZero, cudaEventDisableTiming);
        cudaFuncSetAttribute(k_gemm_fused, cudaFuncAttributeMaxDynamicSharedMemorySize, GEMM_SMEM_BYTES);
    }

    // fork: side stream does scsq (no mask dep) + wconv (fully independent)
    cudaEventRecord(evFork, 0);
    cudaStreamWaitEvent(sSide, evFork, 0);
    k_scsq<<<(NROWS + B_ * LQ_) / 8, 256, 0, sSide>>>(ctx, qry, wsim);
    k_wconv<<<dim3(32, 32, 2), 256, 0, sSide>>>(wi, wo);
    cudaEventRecord(evSide, sSide);

    // main: mask prolog chain; k_zero overlapped on its own stream
    k_detect<<<1, 256>>>((const unsigned int*)cm);
    cudaEventRecord(evDet, 0);
    cudaStreamWaitEvent(sZero, evDet, 0);
    k_zero<<<NROWS, 256, 0, sZero>>>(cm, out);
    cudaEventRecord(evZero, sZero);

    k_count<<<B_, 256>>>(cm);
    k_off<<<1, 128>>>();
    k_fill<<<B_, 256>>>(cm);

    // join side (attn needs g_sc/g_sq; gemm needs W converted)
    cudaStreamWaitEvent(0, evSide, 0);
    k_attn<<<dim3(32, B_), 256>>>(ctx, qry, qm, wsim, bsim);
    k_q2cw<<<B_, 256>>>();
    k_q2cp<<<dim3(32, B_), 256>>>(ctx);
    k_q2cf<<<B_, 256>>>();
    k_buildX<<<NROWS, 256>>>(ctx);
    cudaStreamWaitEvent(0, evZero, 0);
    k_gemm_fused<<<GEMM_GRID, 256, GEMM_SMEM_BYTES>>>(bi, bo, out);
}